// round 3
// baseline (speedup 1.0000x reference)
#include <cuda_runtime.h>

#define NUM_NET 2
#define V 100000
#define D 128
#define B 4096
#define K 5
#define NS 10

#define NBLOCKS 2048   // 16384 warps / 8 warps-per-block
#define NTHREADS 256

__device__ float g_part[NBLOCKS];
__device__ int   g_count = 0;

__device__ __forceinline__ float logsig_fast(float x) {
    // log(sigmoid(x)) = min(x,0) - log(1 + exp(-|x|)); fast-math (err ~1e-6 vs 1e-3 budget)
    return fminf(x, 0.0f) - __logf(1.0f + __expf(-fabsf(x)));
}

__device__ __forceinline__ float dot4(float4 a, float4 b) {
    return fmaf(a.x, b.x, fmaf(a.y, b.y, fmaf(a.z, b.z, a.w * b.w)));
}

// Sum of logsig(sign * (ctx_row . node_emb)) over M gathered rows,
// processed CH rows at a time with independent load/reduce chains.
// M, CH compile-time -> fully unrolled.
template<int M, int CH, bool NEG>
__device__ __forceinline__ float rows_sum(const float* __restrict__ tab,
                                          const int* __restrict__ idx,
                                          float4 ne, int lane) {
    static_assert(M % CH == 0, "");
    float a = 0.0f;
    #pragma unroll
    for (int m = 0; m < M; m += CH) {
        float4 c[CH];
        #pragma unroll
        for (int u = 0; u < CH; u++) {
            int id = __ldg(idx + m + u);
            c[u] = __ldg(reinterpret_cast<const float4*>(tab + (size_t)id * D) + lane);
        }
        float s[CH];
        #pragma unroll
        for (int u = 0; u < CH; u++) s[u] = dot4(ne, c[u]);
        #pragma unroll
        for (int off = 16; off; off >>= 1) {
            #pragma unroll
            for (int u = 0; u < CH; u++)
                s[u] += __shfl_xor_sync(0xffffffffu, s[u], off);
        }
        #pragma unroll
        for (int u = 0; u < CH; u++) a += logsig_fast(NEG ? -s[u] : s[u]);
    }
    return a;
}

__global__ void __launch_bounds__(NTHREADS)
loss_kernel(const float* __restrict__ node_tables,
            const float* __restrict__ neigh_tables,
            const int* __restrict__ nodes_idx,
            const int* __restrict__ neigh_idx,
            const int* __restrict__ role_idx,
            const int* __restrict__ neg_main,
            const int* __restrict__ neg_node,
            const int* __restrict__ neg_cross,
            const int* __restrict__ neg_role,
            float* __restrict__ out) {
    const int lane = threadIdx.x & 31;
    const int wid  = threadIdx.x >> 5;
    const int gw   = blockIdx.x * (NTHREADS >> 5) + wid;   // 0 .. 16383

    const int pair = gw >> 1;          // (i, b) id, 0 .. 8191
    const int half = gw & 1;
    const int i = pair / B;
    const int b = pair % B;
    const int j = 1 - i;
    const size_t VD = (size_t)V * D;

    const float* nt_i = node_tables  + (size_t)i * VD;
    const float* nt_j = node_tables  + (size_t)j * VD;
    const float* gt_i = neigh_tables + (size_t)i * VD;
    const float* gt_j = neigh_tables + (size_t)j * VD;

    // node embedding for (i, b): 4 floats per lane
    const int nid = __ldg(nodes_idx + i * B + b);
    const float4 ne = __ldg(reinterpret_cast<const float4*>(nt_i + (size_t)nid * D) + lane);

    // total = -(1/10) * sum_t w_t * [ pos_mean + neg_sum_mean ]
    const float CB = 1.0f / (10.0f * (float)B);
    const float WH = 0.1f;

    float acc = 0.0f;
    if (half == 0) {
        // term 1: main SGNS on view i  (5 pos + 50 neg)
        acc += rows_sum<K, 5, false>(gt_i, neigh_idx + (i * B + b) * K, ne, lane) * (-CB / (float)K);
        acc += rows_sum<K * NS, 10, true>(gt_i, neg_main + (size_t)(i * B + b) * (K * NS), ne, lane) * (-CB);
        // term 2: cross-view node alignment  (1 pos + 10 neg)
        acc += rows_sum<1, 1, false>(nt_j, nodes_idx + i * B + b, ne, lane) * (-WH * CB);
        acc += rows_sum<NS, 10, true>(nt_j, neg_node + (size_t)((i * NUM_NET + j) * B + b) * NS, ne, lane) * (-WH * CB);
    } else {
        // term 3: cross-view neighbor loss  (5 pos + 50 neg)
        acc += rows_sum<K, 5, false>(gt_j, neigh_idx + (i * B + b) * K, ne, lane) * (-WH * CB / (float)K);
        acc += rows_sum<K * NS, 10, true>(gt_j, neg_cross + (size_t)((i * NUM_NET + j) * B + b) * (K * NS), ne, lane) * (-WH * CB);
        // terms 4,5: role-based losses, j2 in {0,1}  (2 × (1 pos + 10 neg))
        #pragma unroll
        for (int j2 = 0; j2 < NUM_NET; j2++) {
            const float* nt = node_tables + (size_t)j2 * VD;
            acc += rows_sum<1, 1, false>(nt, role_idx + (i * NUM_NET + j2) * B + b, ne, lane) * (-WH * CB);
            acc += rows_sum<NS, 10, true>(nt, neg_role + (size_t)((i * NUM_NET + j2) * B + b) * NS, ne, lane) * (-WH * CB);
        }
    }

    __shared__ float sacc[NTHREADS >> 5];
    __shared__ int s_last;
    if (lane == 0) sacc[wid] = acc;
    __syncthreads();
    if (threadIdx.x == 0) {
        float t = 0.0f;
        #pragma unroll
        for (int w = 0; w < (NTHREADS >> 5); w++) t += sacc[w];
        g_part[blockIdx.x] = t;       // always written: no zero-init needed
        __threadfence();
        int c = atomicAdd(&g_count, 1);
        s_last = (c == NBLOCKS - 1);
    }
    __syncthreads();

    // last block to finish reduces all partials (deterministic: fixed read order)
    if (s_last) {
        __shared__ double sh[NTHREADS >> 5];
        double t = 0.0;
        for (int k2 = threadIdx.x; k2 < NBLOCKS; k2 += NTHREADS)
            t += (double)g_part[k2];
        #pragma unroll
        for (int off = 16; off; off >>= 1)
            t += __shfl_xor_sync(0xffffffffu, t, off);
        if (lane == 0) sh[wid] = t;
        __syncthreads();
        if (threadIdx.x == 0) {
            double v = 0.0;
            #pragma unroll
            for (int w = 0; w < (NTHREADS >> 5); w++) v += sh[w];
            out[0] = (float)v;
            g_count = 0;              // reset for next graph replay
        }
    }
}

extern "C" void kernel_launch(void* const* d_in, const int* in_sizes, int n_in,
                              void* d_out, int out_size) {
    const float* node_tables  = (const float*)d_in[0];
    const float* neigh_tables = (const float*)d_in[1];
    const int*   nodes_idx    = (const int*)d_in[2];
    const int*   neigh_idx    = (const int*)d_in[3];
    const int*   role_idx     = (const int*)d_in[4];
    const int*   neg_main     = (const int*)d_in[5];
    const int*   neg_node     = (const int*)d_in[6];
    const int*   neg_cross    = (const int*)d_in[7];
    const int*   neg_role     = (const int*)d_in[8];

    (void)in_sizes; (void)n_in; (void)out_size;

    loss_kernel<<<NBLOCKS, NTHREADS>>>(node_tables, neigh_tables, nodes_idx,
                                       neigh_idx, role_idx, neg_main,
                                       neg_node, neg_cross, neg_role,
                                       (float*)d_out);
}

// round 4
// speedup vs baseline: 1.3089x; 1.3089x over previous
#include <cuda_runtime.h>

#define NUM_NET 2
#define V 100000
#define D 128
#define B 4096
#define K 5
#define NS 10

#define NBLOCKS 4096   // 32768 warps / 8 warps-per-block
#define NTHREADS 256

__device__ float g_part[NBLOCKS];

__device__ __forceinline__ float logsig_fast(float x) {
    // log(sigmoid(x)) = min(x,0) - log(1 + exp(-|x|)); fast-math (err ~1e-6 vs 1e-3 budget)
    return fminf(x, 0.0f) - __logf(1.0f + __expf(-fabsf(x)));
}

__device__ __forceinline__ float dot4(float4 a, float4 b) {
    return fmaf(a.x, b.x, fmaf(a.y, b.y, fmaf(a.z, b.z, a.w * b.w)));
}

// Sum of logsig(sign*(row . ne)) over M rows, 5 independent chains per batch.
// M is a runtime multiple of 5 -> small code, deep MLP.
template<bool NEG>
__device__ __forceinline__ float rows_sum5(const float* __restrict__ tab,
                                           const int* __restrict__ idx,
                                           int M, float4 ne, int lane) {
    float a = 0.0f;
    for (int m = 0; m < M; m += 5) {
        float4 c[5];
        #pragma unroll
        for (int u = 0; u < 5; u++) {
            int id = __ldg(idx + m + u);
            c[u] = __ldg(reinterpret_cast<const float4*>(tab + (size_t)id * D) + lane);
        }
        float s[5];
        #pragma unroll
        for (int u = 0; u < 5; u++) s[u] = dot4(ne, c[u]);
        #pragma unroll
        for (int off = 16; off; off >>= 1) {
            #pragma unroll
            for (int u = 0; u < 5; u++)
                s[u] += __shfl_xor_sync(0xffffffffu, s[u], off);
        }
        #pragma unroll
        for (int u = 0; u < 5; u++) a += logsig_fast(NEG ? -s[u] : s[u]);
    }
    return a;
}

// Single-row positive term.
__device__ __forceinline__ float row_one(const float* __restrict__ tab,
                                         const int* __restrict__ idx,
                                         float4 ne, int lane) {
    int id = __ldg(idx);
    float4 c = __ldg(reinterpret_cast<const float4*>(tab + (size_t)id * D) + lane);
    float s = dot4(ne, c);
    #pragma unroll
    for (int off = 16; off; off >>= 1)
        s += __shfl_xor_sync(0xffffffffu, s, off);
    return logsig_fast(s);
}

__global__ void __launch_bounds__(NTHREADS)
loss_kernel(const float* __restrict__ node_tables,
            const float* __restrict__ neigh_tables,
            const int* __restrict__ nodes_idx,
            const int* __restrict__ neigh_idx,
            const int* __restrict__ role_idx,
            const int* __restrict__ neg_main,
            const int* __restrict__ neg_node,
            const int* __restrict__ neg_cross,
            const int* __restrict__ neg_role) {
    const int lane = threadIdx.x & 31;
    const int wid  = threadIdx.x >> 5;
    const int gw   = blockIdx.x * (NTHREADS >> 5) + wid;   // 0 .. 32767

    const int pair = gw >> 2;          // (i, b) id, 0 .. 8191
    const int q    = gw & 3;           // quarter of the work
    const int i = pair / B;
    const int b = pair % B;
    const int j = 1 - i;
    const size_t VD = (size_t)V * D;

    const float* nt_i = node_tables  + (size_t)i * VD;
    const float* nt_j = node_tables  + (size_t)j * VD;
    const float* gt_i = neigh_tables + (size_t)i * VD;
    const float* gt_j = neigh_tables + (size_t)j * VD;

    // node embedding for (i, b): 4 floats per lane
    const int nid = __ldg(nodes_idx + i * B + b);
    const float4 ne = __ldg(reinterpret_cast<const float4*>(nt_i + (size_t)nid * D) + lane);

    // total = -(1/10) * sum_t w_t * [ pos_mean + neg_sum_mean ]
    const float CB = 1.0f / (10.0f * (float)B);
    const float WH = 0.1f;

    const int* nm = neg_main  + (size_t)(i * B + b) * (K * NS);
    const int* nc = neg_cross + (size_t)((i * NUM_NET + j) * B + b) * (K * NS);

    float acc = 0.0f;
    if (q == 0) {
        // t1 pos (5) + neg_main[0:30]
        acc += rows_sum5<false>(gt_i, neigh_idx + (i * B + b) * K, K, ne, lane) * (-CB / (float)K);
        acc += rows_sum5<true>(gt_i, nm, 30, ne, lane) * (-CB);
    } else if (q == 1) {
        // neg_main[30:50] + t2 (1 pos + 10 neg)
        acc += rows_sum5<true>(gt_i, nm + 30, 20, ne, lane) * (-CB);
        acc += row_one(nt_j, nodes_idx + i * B + b, ne, lane) * (-WH * CB);
        acc += rows_sum5<true>(nt_j, neg_node + (size_t)((i * NUM_NET + j) * B + b) * NS, NS, ne, lane) * (-WH * CB);
    } else if (q == 2) {
        // t3 pos (5) + neg_cross[0:30]
        acc += rows_sum5<false>(gt_j, neigh_idx + (i * B + b) * K, K, ne, lane) * (-WH * CB / (float)K);
        acc += rows_sum5<true>(gt_j, nc, 30, ne, lane) * (-WH * CB);
    } else {
        // neg_cross[30:50] + roles (2 x (1 pos + 10 neg))
        acc += rows_sum5<true>(gt_j, nc + 30, 20, ne, lane) * (-WH * CB);
        #pragma unroll
        for (int j2 = 0; j2 < NUM_NET; j2++) {
            const float* nt = node_tables + (size_t)j2 * VD;
            acc += row_one(nt, role_idx + (i * NUM_NET + j2) * B + b, ne, lane) * (-WH * CB);
            acc += rows_sum5<true>(nt, neg_role + (size_t)((i * NUM_NET + j2) * B + b) * NS, NS, ne, lane) * (-WH * CB);
        }
    }

    __shared__ float sacc[NTHREADS >> 5];
    if (lane == 0) sacc[wid] = acc;
    __syncthreads();
    if (threadIdx.x == 0) {
        float t = 0.0f;
        #pragma unroll
        for (int w = 0; w < (NTHREADS >> 5); w++) t += sacc[w];
        g_part[blockIdx.x] = t;   // always written: no zero-init needed
    }
}

__global__ void __launch_bounds__(1024)
finalize_kernel(float* __restrict__ out) {
    __shared__ double sh[32];
    double t = 0.0;
    for (int k = threadIdx.x; k < NBLOCKS; k += 1024)
        t += (double)g_part[k];
    #pragma unroll
    for (int off = 16; off; off >>= 1)
        t += __shfl_xor_sync(0xffffffffu, t, off);
    if ((threadIdx.x & 31) == 0) sh[threadIdx.x >> 5] = t;
    __syncthreads();
    if (threadIdx.x < 32) {
        double v = sh[threadIdx.x];
        #pragma unroll
        for (int off = 16; off; off >>= 1)
            v += __shfl_xor_sync(0xffffffffu, v, off);
        if (threadIdx.x == 0) out[0] = (float)v;
    }
}

extern "C" void kernel_launch(void* const* d_in, const int* in_sizes, int n_in,
                              void* d_out, int out_size) {
    const float* node_tables  = (const float*)d_in[0];
    const float* neigh_tables = (const float*)d_in[1];
    const int*   nodes_idx    = (const int*)d_in[2];
    const int*   neigh_idx    = (const int*)d_in[3];
    const int*   role_idx     = (const int*)d_in[4];
    const int*   neg_main     = (const int*)d_in[5];
    const int*   neg_node     = (const int*)d_in[6];
    const int*   neg_cross    = (const int*)d_in[7];
    const int*   neg_role     = (const int*)d_in[8];

    (void)in_sizes; (void)n_in; (void)out_size;

    loss_kernel<<<NBLOCKS, NTHREADS>>>(node_tables, neigh_tables, nodes_idx,
                                       neigh_idx, role_idx, neg_main,
                                       neg_node, neg_cross, neg_role);
    finalize_kernel<<<1, 1024>>>((float*)d_out);
}

// round 5
// speedup vs baseline: 1.3139x; 1.0038x over previous
#include <cuda_runtime.h>

#define NUM_NET 2
#define V 100000
#define D 128
#define B 4096
#define K 5
#define NS 10

#define NBLOCKS 4096   // 32768 warps / 8 warps-per-block
#define NTHREADS 256

__device__ float g_part[NBLOCKS];
__device__ int   g_count = 0;

__device__ __forceinline__ float logsig_fast(float x) {
    // log(sigmoid(x)) = min(x,0) - log(1 + exp(-|x|)); fast-math (err ~1e-6 vs 1e-3 budget)
    return fminf(x, 0.0f) - __logf(1.0f + __expf(-fabsf(x)));
}

__device__ __forceinline__ float dot4(float4 a, float4 b) {
    return fmaf(a.x, b.x, fmaf(a.y, b.y, fmaf(a.z, b.z, a.w * b.w)));
}

// Sum of logsig(sign*(row . ne)) over M rows, 5 independent chains per batch.
// M is a runtime multiple of 5 -> small code, deep MLP.
template<bool NEG>
__device__ __forceinline__ float rows_sum5(const float* __restrict__ tab,
                                           const int* __restrict__ idx,
                                           int M, float4 ne, int lane) {
    float a = 0.0f;
    for (int m = 0; m < M; m += 5) {
        float4 c[5];
        #pragma unroll
        for (int u = 0; u < 5; u++) {
            int id = __ldg(idx + m + u);
            c[u] = __ldg(reinterpret_cast<const float4*>(tab + (size_t)id * D) + lane);
        }
        float s[5];
        #pragma unroll
        for (int u = 0; u < 5; u++) s[u] = dot4(ne, c[u]);
        #pragma unroll
        for (int off = 16; off; off >>= 1) {
            #pragma unroll
            for (int u = 0; u < 5; u++)
                s[u] += __shfl_xor_sync(0xffffffffu, s[u], off);
        }
        #pragma unroll
        for (int u = 0; u < 5; u++) a += logsig_fast(NEG ? -s[u] : s[u]);
    }
    return a;
}

// Single-row positive term.
__device__ __forceinline__ float row_one(const float* __restrict__ tab,
                                         const int* __restrict__ idx,
                                         float4 ne, int lane) {
    int id = __ldg(idx);
    float4 c = __ldg(reinterpret_cast<const float4*>(tab + (size_t)id * D) + lane);
    float s = dot4(ne, c);
    #pragma unroll
    for (int off = 16; off; off >>= 1)
        s += __shfl_xor_sync(0xffffffffu, s, off);
    return logsig_fast(s);
}

__global__ void __launch_bounds__(NTHREADS)
loss_kernel(const float* __restrict__ node_tables,
            const float* __restrict__ neigh_tables,
            const int* __restrict__ nodes_idx,
            const int* __restrict__ neigh_idx,
            const int* __restrict__ role_idx,
            const int* __restrict__ neg_main,
            const int* __restrict__ neg_node,
            const int* __restrict__ neg_cross,
            const int* __restrict__ neg_role,
            float* __restrict__ out) {
    const int lane = threadIdx.x & 31;
    const int wid  = threadIdx.x >> 5;
    const int gw   = blockIdx.x * (NTHREADS >> 5) + wid;   // 0 .. 32767

    const int pair = gw >> 2;          // (i, b) id, 0 .. 8191
    const int q    = gw & 3;           // quarter of the work
    const int i = pair / B;
    const int b = pair % B;
    const int j = 1 - i;
    const size_t VD = (size_t)V * D;

    const float* nt_i = node_tables  + (size_t)i * VD;
    const float* nt_j = node_tables  + (size_t)j * VD;
    const float* gt_i = neigh_tables + (size_t)i * VD;
    const float* gt_j = neigh_tables + (size_t)j * VD;

    // node embedding for (i, b): 4 floats per lane
    const int nid = __ldg(nodes_idx + i * B + b);
    const float4 ne = __ldg(reinterpret_cast<const float4*>(nt_i + (size_t)nid * D) + lane);

    // total = -(1/10) * sum_t w_t * [ pos_mean + neg_sum_mean ]
    const float CB = 1.0f / (10.0f * (float)B);
    const float WH = 0.1f;

    const int* nm  = neg_main  + (size_t)(i * B + b) * (K * NS);
    const int* nc  = neg_cross + (size_t)((i * NUM_NET + j) * B + b) * (K * NS);
    // role term for j2 = 1 (split across q1/q3 for balance)
    const int* nr1 = neg_role  + (size_t)((i * NUM_NET + 1) * B + b) * NS;

    float acc = 0.0f;
    if (q == 0) {
        // t1 pos (5) + neg_main[0:30]                          -> 35 rows
        acc += rows_sum5<false>(gt_i, neigh_idx + (i * B + b) * K, K, ne, lane) * (-CB / (float)K);
        acc += rows_sum5<true>(gt_i, nm, 30, ne, lane) * (-CB);
    } else if (q == 1) {
        // neg_main[30:50] + t2 (1+10) + role1 neg[0:5]         -> 36 rows
        acc += rows_sum5<true>(gt_i, nm + 30, 20, ne, lane) * (-CB);
        acc += row_one(nt_j, nodes_idx + i * B + b, ne, lane) * (-WH * CB);
        acc += rows_sum5<true>(nt_j, neg_node + (size_t)((i * NUM_NET + j) * B + b) * NS, NS, ne, lane) * (-WH * CB);
        acc += rows_sum5<true>(node_tables + VD, nr1, 5, ne, lane) * (-WH * CB);
    } else if (q == 2) {
        // t3 pos (5) + neg_cross[0:30]                         -> 35 rows
        acc += rows_sum5<false>(gt_j, neigh_idx + (i * B + b) * K, K, ne, lane) * (-WH * CB / (float)K);
        acc += rows_sum5<true>(gt_j, nc, 30, ne, lane) * (-WH * CB);
    } else {
        // neg_cross[30:50] + role0 (1+10) + role1 pos + role1 neg[5:10]  -> 37 rows
        acc += rows_sum5<true>(gt_j, nc + 30, 20, ne, lane) * (-WH * CB);
        acc += row_one(node_tables, role_idx + (i * NUM_NET + 0) * B + b, ne, lane) * (-WH * CB);
        acc += rows_sum5<true>(node_tables, neg_role + (size_t)((i * NUM_NET + 0) * B + b) * NS, NS, ne, lane) * (-WH * CB);
        acc += row_one(node_tables + VD, role_idx + (i * NUM_NET + 1) * B + b, ne, lane) * (-WH * CB);
        acc += rows_sum5<true>(node_tables + VD, nr1 + 5, 5, ne, lane) * (-WH * CB);
    }

    __shared__ float sacc[NTHREADS >> 5];
    __shared__ int s_last;
    if (lane == 0) sacc[wid] = acc;
    __syncthreads();
    if (threadIdx.x == 0) {
        float t = 0.0f;
        #pragma unroll
        for (int w = 0; w < (NTHREADS >> 5); w++) t += sacc[w];
        g_part[blockIdx.x] = t;       // always written: no zero-init needed
        __threadfence();
        int c = atomicAdd(&g_count, 1);
        s_last = (c == NBLOCKS - 1);
    }
    __syncthreads();

    // the last block to arrive reduces all partials; fixed read order -> deterministic
    if (s_last) {
        __threadfence();              // acquire: see all g_part writes
        __shared__ double sh[NTHREADS >> 5];
        double t = 0.0;
        for (int k2 = threadIdx.x; k2 < NBLOCKS; k2 += NTHREADS)
            t += (double)g_part[k2];
        #pragma unroll
        for (int off = 16; off; off >>= 1)
            t += __shfl_xor_sync(0xffffffffu, t, off);
        if (lane == 0) sh[wid] = t;
        __syncthreads();
        if (threadIdx.x == 0) {
            double v = 0.0;
            #pragma unroll
            for (int w = 0; w < (NTHREADS >> 5); w++) v += sh[w];
            out[0] = (float)v;
            g_count = 0;              // reset for next graph replay
        }
    }
}

extern "C" void kernel_launch(void* const* d_in, const int* in_sizes, int n_in,
                              void* d_out, int out_size) {
    const float* node_tables  = (const float*)d_in[0];
    const float* neigh_tables = (const float*)d_in[1];
    const int*   nodes_idx    = (const int*)d_in[2];
    const int*   neigh_idx    = (const int*)d_in[3];
    const int*   role_idx     = (const int*)d_in[4];
    const int*   neg_main     = (const int*)d_in[5];
    const int*   neg_node     = (const int*)d_in[6];
    const int*   neg_cross    = (const int*)d_in[7];
    const int*   neg_role     = (const int*)d_in[8];

    (void)in_sizes; (void)n_in; (void)out_size;

    loss_kernel<<<NBLOCKS, NTHREADS>>>(node_tables, neigh_tables, nodes_idx,
                                       neigh_idx, role_idx, neg_main,
                                       neg_node, neg_cross, neg_role,
                                       (float*)d_out);
}

// round 6
// speedup vs baseline: 1.3496x; 1.0272x over previous
#include <cuda_runtime.h>

#define NUM_NET 2
#define V 100000
#define D 128
#define B 4096
#define K 5
#define NS 10

#define NTHREADS 256
#define WPB (NTHREADS >> 5)
#define NEIGH_WARPS (NUM_NET * B * 4)   // 32768: 4 warps per (i,b) on neigh tables
#define NODE_WARPS  (NUM_NET * B)       // 8192:  1 warp per (i,b) on node tables
#define NBLOCKS ((NEIGH_WARPS + NODE_WARPS) / WPB)   // 5120

__device__ float g_part[NBLOCKS];
__device__ int   g_count = 0;

__device__ __forceinline__ float logsig_fast(float x) {
    // log(sigmoid(x)) = min(x,0) - log(1 + exp(-|x|)); fast-math (err ~1e-6 vs 1e-3 budget)
    return fminf(x, 0.0f) - __logf(1.0f + __expf(-fabsf(x)));
}

__device__ __forceinline__ float dot4(float4 a, float4 b) {
    return fmaf(a.x, b.x, fmaf(a.y, b.y, fmaf(a.z, b.z, a.w * b.w)));
}

// Sum of logsig(sign*(row . ne)) over M rows, 5 independent chains per batch.
// M is a runtime multiple of 5 -> small code, deep MLP.
template<bool NEG>
__device__ __forceinline__ float rows_sum5(const float* __restrict__ tab,
                                           const int* __restrict__ idx,
                                           int M, float4 ne, int lane) {
    float a = 0.0f;
    for (int m = 0; m < M; m += 5) {
        float4 c[5];
        #pragma unroll
        for (int u = 0; u < 5; u++) {
            int id = __ldg(idx + m + u);
            c[u] = __ldg(reinterpret_cast<const float4*>(tab + (size_t)id * D) + lane);
        }
        float s[5];
        #pragma unroll
        for (int u = 0; u < 5; u++) s[u] = dot4(ne, c[u]);
        #pragma unroll
        for (int off = 16; off; off >>= 1) {
            #pragma unroll
            for (int u = 0; u < 5; u++)
                s[u] += __shfl_xor_sync(0xffffffffu, s[u], off);
        }
        #pragma unroll
        for (int u = 0; u < 5; u++) a += logsig_fast(NEG ? -s[u] : s[u]);
    }
    return a;
}

// Three single-row positive terms from three (table, index) pairs, batched.
__device__ __forceinline__ float pos3(const float* __restrict__ t0, int i0,
                                      const float* __restrict__ t1, int i1,
                                      const float* __restrict__ t2, int i2,
                                      float4 ne, int lane) {
    float4 c0 = __ldg(reinterpret_cast<const float4*>(t0 + (size_t)i0 * D) + lane);
    float4 c1 = __ldg(reinterpret_cast<const float4*>(t1 + (size_t)i1 * D) + lane);
    float4 c2 = __ldg(reinterpret_cast<const float4*>(t2 + (size_t)i2 * D) + lane);
    float s0 = dot4(ne, c0), s1 = dot4(ne, c1), s2 = dot4(ne, c2);
    #pragma unroll
    for (int off = 16; off; off >>= 1) {
        s0 += __shfl_xor_sync(0xffffffffu, s0, off);
        s1 += __shfl_xor_sync(0xffffffffu, s1, off);
        s2 += __shfl_xor_sync(0xffffffffu, s2, off);
    }
    return logsig_fast(s0) + logsig_fast(s1) + logsig_fast(s2);
}

__global__ void __launch_bounds__(NTHREADS)
loss_kernel(const float* __restrict__ node_tables,
            const float* __restrict__ neigh_tables,
            const int* __restrict__ nodes_idx,
            const int* __restrict__ neigh_idx,
            const int* __restrict__ role_idx,
            const int* __restrict__ neg_main,
            const int* __restrict__ neg_node,
            const int* __restrict__ neg_cross,
            const int* __restrict__ neg_role,
            float* __restrict__ out) {
    const int lane = threadIdx.x & 31;
    const int wid  = threadIdx.x >> 5;
    const int gw   = blockIdx.x * WPB + wid;
    const size_t VD = (size_t)V * D;

    // total = -(1/10) * sum_t w_t * [ pos_mean + neg_sum_mean ]
    const float CB = 1.0f / (10.0f * (float)B);
    const float WH = 0.1f;

    float acc = 0.0f;

    if (gw < NEIGH_WARPS) {
        // ---- phase 1: neigh-table terms (t1, t3); L2 holds the two neigh tables ----
        const int pair = gw >> 2;      // (i, b)
        const int sub  = gw & 3;
        const int i = pair / B;
        const int b = pair % B;
        const int j = 1 - i;

        const float* gt_i = neigh_tables + (size_t)i * VD;
        const float* gt_j = neigh_tables + (size_t)j * VD;

        const int nid = __ldg(nodes_idx + i * B + b);
        const float4 ne = __ldg(reinterpret_cast<const float4*>(
            node_tables + (size_t)i * VD + (size_t)nid * D) + lane);

        const int* nm = neg_main  + (size_t)(i * B + b) * (K * NS);
        const int* nc = neg_cross + (size_t)((i * NUM_NET + j) * B + b) * (K * NS);

        if (sub == 0) {
            // t1 pos (5) + neg_main[0:25]   -> 30 rows
            acc += rows_sum5<false>(gt_i, neigh_idx + (i * B + b) * K, K, ne, lane) * (-CB / (float)K);
            acc += rows_sum5<true>(gt_i, nm, 25, ne, lane) * (-CB);
        } else if (sub == 1) {
            // neg_main[25:50] + t3 pos (5)  -> 30 rows
            acc += rows_sum5<true>(gt_i, nm + 25, 25, ne, lane) * (-CB);
            acc += rows_sum5<false>(gt_j, neigh_idx + (i * B + b) * K, K, ne, lane) * (-WH * CB / (float)K);
        } else if (sub == 2) {
            acc += rows_sum5<true>(gt_j, nc, 25, ne, lane) * (-WH * CB);
        } else {
            acc += rows_sum5<true>(gt_j, nc + 25, 25, ne, lane) * (-WH * CB);
        }
    } else {
        // ---- phase 2: node-table terms (t2, roles); runs in the last wave ----
        const int pair = gw - NEIGH_WARPS;   // (i, b)
        const int i = pair / B;
        const int b = pair % B;
        const int j = 1 - i;

        const float* nt_j = node_tables + (size_t)j * VD;

        const int nid = __ldg(nodes_idx + i * B + b);
        const float4 ne = __ldg(reinterpret_cast<const float4*>(
            node_tables + (size_t)i * VD + (size_t)nid * D) + lane);

        // three positives batched: t2 pos + role(j2=0) pos + role(j2=1) pos
        acc += pos3(nt_j, __ldg(nodes_idx + i * B + b),
                    node_tables,      __ldg(role_idx + (i * NUM_NET + 0) * B + b),
                    node_tables + VD, __ldg(role_idx + (i * NUM_NET + 1) * B + b),
                    ne, lane) * (-WH * CB);
        // negatives: 3 x 10 rows
        acc += rows_sum5<true>(nt_j, neg_node + (size_t)((i * NUM_NET + j) * B + b) * NS, NS, ne, lane) * (-WH * CB);
        acc += rows_sum5<true>(node_tables,      neg_role + (size_t)((i * NUM_NET + 0) * B + b) * NS, NS, ne, lane) * (-WH * CB);
        acc += rows_sum5<true>(node_tables + VD, neg_role + (size_t)((i * NUM_NET + 1) * B + b) * NS, NS, ne, lane) * (-WH * CB);
    }

    __shared__ float sacc[WPB];
    __shared__ int s_last;
    if (lane == 0) sacc[wid] = acc;
    __syncthreads();
    if (threadIdx.x == 0) {
        float t = 0.0f;
        #pragma unroll
        for (int w = 0; w < WPB; w++) t += sacc[w];
        g_part[blockIdx.x] = t;       // always written: no zero-init needed
        __threadfence();
        int c = atomicAdd(&g_count, 1);
        s_last = (c == NBLOCKS - 1);
    }
    __syncthreads();

    // the last block to arrive reduces all partials; fixed read order -> deterministic
    if (s_last) {
        __threadfence();              // acquire: see all g_part writes
        __shared__ double sh[WPB];
        double t = 0.0;
        for (int k2 = threadIdx.x; k2 < NBLOCKS; k2 += NTHREADS)
            t += (double)g_part[k2];
        #pragma unroll
        for (int off = 16; off; off >>= 1)
            t += __shfl_xor_sync(0xffffffffu, t, off);
        if (lane == 0) sh[wid] = t;
        __syncthreads();
        if (threadIdx.x == 0) {
            double v = 0.0;
            #pragma unroll
            for (int w = 0; w < WPB; w++) v += sh[w];
            out[0] = (float)v;
            g_count = 0;              // reset for next graph replay
        }
    }
}

extern "C" void kernel_launch(void* const* d_in, const int* in_sizes, int n_in,
                              void* d_out, int out_size) {
    const float* node_tables  = (const float*)d_in[0];
    const float* neigh_tables = (const float*)d_in[1];
    const int*   nodes_idx    = (const int*)d_in[2];
    const int*   neigh_idx    = (const int*)d_in[3];
    const int*   role_idx     = (const int*)d_in[4];
    const int*   neg_main     = (const int*)d_in[5];
    const int*   neg_node     = (const int*)d_in[6];
    const int*   neg_cross    = (const int*)d_in[7];
    const int*   neg_role     = (const int*)d_in[8];

    (void)in_sizes; (void)n_in; (void)out_size;

    loss_kernel<<<NBLOCKS, NTHREADS>>>(node_tables, neigh_tables, nodes_idx,
                                       neigh_idx, role_idx, neg_main,
                                       neg_node, neg_cross, neg_role,
                                       (float*)d_out);
}